// round 1
// baseline (speedup 1.0000x reference)
#include <cuda_runtime.h>

#define BATCH 8
#define SLEN  2048
#define DIM   1024
#define WIN   20
#define NK    41          // window width = 2*WIN+1

// Scratch: QT[b,q,d] = sum_j Q[b,q,j] * W[j,d]   (64 MB static device scratch)
__device__ float g_qt[(size_t)BATCH * SLEN * DIM];

// ---------------------------------------------------------------------------
// SGEMM: g_qt[M,N] = A[M,K] @ B[K,N],  M=16384, N=K=1024, fp32.
// BM=BN=128, BK=16, 256 threads, 8x8 register tile per thread.
// ---------------------------------------------------------------------------
__global__ __launch_bounds__(256) void sgemm_qt_kernel(const float* __restrict__ A,
                                                       const float* __restrict__ B) {
    __shared__ float As[16][128];
    __shared__ float Bs[16][128];
    const int tid = threadIdx.x;
    const int bm  = blockIdx.y * 128;
    const int bn  = blockIdx.x * 128;
    const int ty  = tid >> 4;
    const int tx  = tid & 15;

    float acc[8][8];
#pragma unroll
    for (int i = 0; i < 8; i++)
#pragma unroll
        for (int j = 0; j < 8; j++) acc[i][j] = 0.f;

    for (int k0 = 0; k0 < DIM; k0 += 16) {
        // A tile: 128 rows x 16 cols, float4 per thread x2, store transposed
#pragma unroll
        for (int i = 0; i < 2; i++) {
            int f = tid + i * 256;
            int r = f >> 2, kc = (f & 3) << 2;
            float4 v = *(const float4*)(A + (size_t)(bm + r) * DIM + k0 + kc);
            As[kc + 0][r] = v.x;
            As[kc + 1][r] = v.y;
            As[kc + 2][r] = v.z;
            As[kc + 3][r] = v.w;
        }
        // B tile: 16 rows x 128 cols
#pragma unroll
        for (int i = 0; i < 2; i++) {
            int f = tid + i * 256;
            int r = f >> 5, c = (f & 31) << 2;
            *(float4*)&Bs[r][c] = *(const float4*)(B + (size_t)(k0 + r) * DIM + bn + c);
        }
        __syncthreads();
#pragma unroll
        for (int kk = 0; kk < 16; kk++) {
            float a[8], b[8];
            *(float4*)&a[0] = *(float4*)&As[kk][ty * 8];
            *(float4*)&a[4] = *(float4*)&As[kk][ty * 8 + 4];
            *(float4*)&b[0] = *(float4*)&Bs[kk][tx * 8];
            *(float4*)&b[4] = *(float4*)&Bs[kk][tx * 8 + 4];
#pragma unroll
            for (int i = 0; i < 8; i++)
#pragma unroll
                for (int j = 0; j < 8; j++)
                    acc[i][j] = fmaf(a[i], b[j], acc[i][j]);
        }
        __syncthreads();
    }
#pragma unroll
    for (int i = 0; i < 8; i++)
#pragma unroll
        for (int j = 0; j < 8; j += 4) {
            float4 v = make_float4(acc[i][j], acc[i][j + 1], acc[i][j + 2], acc[i][j + 3]);
            *(float4*)(g_qt + (size_t)(bm + ty * 8 + i) * DIM + bn + tx * 8 + j) = v;
        }
}

// ---------------------------------------------------------------------------
// Banded attention: per CTA, QB consecutive queries of one batch.
//   scores s[i][j] = QT[q0+i,:] . K[q0+i-20+j,:]   (j in [0,41))
//   softmax over valid j, then out = sum_j w * K row.
// Keys streamed in DC-wide d-chunks through shared memory (2 passes).
// ---------------------------------------------------------------------------
#define QB   32
#define RT   72           // QB + 2*WIN rows of keys needed
#define RTA  80           // allocated rows (allows unguarded reads for j<48)
#define DC   64
#define KSTR 68           // padded row stride

__global__ __launch_bounds__(256) void band_attn_kernel(const float* __restrict__ keys,
                                                        float* __restrict__ out) {
    __shared__ float qts[QB][DC];
    __shared__ float ks[RTA][KSTR];
    __shared__ float sc[QB][48];

    const int tid = threadIdx.x;
    const int b   = blockIdx.y;
    const int q0  = blockIdx.x * QB;
    const size_t base = (size_t)b * SLEN * DIM;

    // ---------- phase 1: band scores ----------
    const int iq = tid >> 3;           // query index 0..31
    const int j0 = (tid & 7) * 6;      // this thread's 6 consecutive window slots

    float acc[6] = {0.f, 0.f, 0.f, 0.f, 0.f, 0.f};

    for (int dc = 0; dc < DIM; dc += DC) {
        __syncthreads();
        for (int f = tid; f < QB * DC / 4; f += 256) {
            int r = f >> 4, c = (f & 15) << 2;
            *(float4*)&qts[r][c] =
                *(const float4*)(g_qt + base + (size_t)(q0 + r) * DIM + dc + c);
        }
        for (int f = tid; f < RT * DC / 4; f += 256) {
            int r = f >> 4, c = (f & 15) << 2;
            int gr = q0 - WIN + r;
            float4 v = make_float4(0.f, 0.f, 0.f, 0.f);
            if (gr >= 0 && gr < SLEN)
                v = *(const float4*)(keys + base + (size_t)gr * DIM + dc + c);
            *(float4*)&ks[r][c] = v;
        }
        __syncthreads();
        for (int d = 0; d < DC; d += 4) {
            float4 qa = *(float4*)&qts[iq][d];
#pragma unroll
            for (int u = 0; u < 6; u++) {
                int r = iq + j0 + u;                 // <= 31+47=78 < RTA
                float4 kb = *(float4*)&ks[r][d];
                acc[u] = fmaf(qa.x, kb.x, acc[u]);
                acc[u] = fmaf(qa.y, kb.y, acc[u]);
                acc[u] = fmaf(qa.z, kb.z, acc[u]);
                acc[u] = fmaf(qa.w, kb.w, acc[u]);
            }
        }
    }
#pragma unroll
    for (int u = 0; u < 6; u++) {
        int j = j0 + u;
        if (j < NK) sc[iq][j] = acc[u];
    }
    __syncthreads();

    // ---------- phase 2: softmax over the window ----------
    if (tid < QB) {
        int q = q0 + tid;
        float mx = -3.4e38f;
        for (int j = 0; j < NK; j++) {
            int k = q - WIN + j;
            if (k >= 0 && k < SLEN) mx = fmaxf(mx, sc[tid][j]);
        }
        float sum = 0.f;
        for (int j = 0; j < NK; j++) {
            int k = q - WIN + j;
            float e = 0.f;
            if (k >= 0 && k < SLEN) e = __expf(sc[tid][j] - mx);
            sc[tid][j] = e;
            sum += e;
        }
        float inv = 1.f / sum;
        for (int j = 0; j < NK; j++) sc[tid][j] *= inv;
    }

    // ---------- phase 3: out = weights @ keys ----------
    const int ip = tid >> 3;
    const int g  = tid & 7;
    for (int dc = 0; dc < DIM; dc += DC) {
        __syncthreads();   // also covers sc readiness on the first iteration
        for (int f = tid; f < RT * DC / 4; f += 256) {
            int r = f >> 4, c = (f & 15) << 2;
            int gr = q0 - WIN + r;
            float4 v = make_float4(0.f, 0.f, 0.f, 0.f);
            if (gr >= 0 && gr < SLEN)
                v = *(const float4*)(keys + base + (size_t)gr * DIM + dc + c);
            *(float4*)&ks[r][c] = v;
        }
        __syncthreads();
        for (int dd = g * 4; dd < DC; dd += 32) {
            float4 o = make_float4(0.f, 0.f, 0.f, 0.f);
#pragma unroll
            for (int j = 0; j < NK; j++) {
                float w = sc[ip][j];
                float4 kv = *(float4*)&ks[ip + j][dd];
                o.x = fmaf(w, kv.x, o.x);
                o.y = fmaf(w, kv.y, o.y);
                o.z = fmaf(w, kv.z, o.z);
                o.w = fmaf(w, kv.w, o.w);
            }
            *(float4*)(out + base + (size_t)(q0 + ip) * DIM + dc + dd) = o;
        }
    }
}

extern "C" void kernel_launch(void* const* d_in, const int* in_sizes, int n_in,
                              void* d_out, int out_size) {
    const float* queries = (const float*)d_in[0];
    const float* keys    = (const float*)d_in[1];
    const float* W       = (const float*)d_in[2];
    // d_in[3] = b_reduce: adds a per-(b,q) constant to all logits -> softmax-invariant, unused.
    float* out = (float*)d_out;

    dim3 g1(DIM / 128, (BATCH * SLEN) / 128);
    sgemm_qt_kernel<<<g1, 256>>>(queries, W);

    dim3 g2(SLEN / QB, BATCH);
    band_attn_kernel<<<g2, 256>>>(keys, out);
}

// round 3
// speedup vs baseline: 1.5104x; 1.5104x over previous
#include <cuda_runtime.h>
#include <cuda_bf16.h>
#include <cstdint>

#define BATCH 8
#define SLEN  2048
#define DIM   1024
#define WIN   20
#define NK    41
#define MTOT  (BATCH * SLEN)   // 16384

// ---------------- static device scratch (no allocations allowed) ------------
__device__ float         g_qt [(size_t)MTOT * DIM];   // QT = Q @ W   (fp32)
__device__ __nv_bfloat16 g_qhi[(size_t)MTOT * DIM];
__device__ __nv_bfloat16 g_qlo[(size_t)MTOT * DIM];
__device__ __nv_bfloat16 g_wthi[(size_t)DIM * DIM];   // W^T split: [d][j]
__device__ __nv_bfloat16 g_wtlo[(size_t)DIM * DIM];

// ---------------- helpers (plain-sm_103-safe PTX only) -----------------------
__device__ __forceinline__ uint32_t smem_u32(const void* p) {
    uint32_t a;
    asm("{ .reg .u64 t; cvta.to.shared.u64 t, %1; cvt.u32.u64 %0, t; }" : "=r"(a) : "l"(p));
    return a;
}
#define CP_ASYNC16(sd, gp) \
    asm volatile("cp.async.cg.shared.global [%0], [%1], 16;" :: "r"(sd), "l"(gp) : "memory")
#define CP_COMMIT()   asm volatile("cp.async.commit_group;" ::: "memory")
#define CP_WAIT0()    asm volatile("cp.async.wait_group 0;" ::: "memory")
#define CP_WAIT1()    asm volatile("cp.async.wait_group 1;" ::: "memory")

__device__ __forceinline__ void ldsm_x4(uint32_t a, uint32_t& r0, uint32_t& r1,
                                        uint32_t& r2, uint32_t& r3) {
    asm volatile("ldmatrix.sync.aligned.m8n8.x4.shared.b16 {%0,%1,%2,%3}, [%4];"
                 : "=r"(r0), "=r"(r1), "=r"(r2), "=r"(r3) : "r"(a));
}
__device__ __forceinline__ void mma16816(float* c, const uint32_t* a,
                                         uint32_t b0, uint32_t b1) {
    asm volatile(
        "mma.sync.aligned.m16n8k16.row.col.f32.bf16.bf16.f32 "
        "{%0,%1,%2,%3}, {%4,%5,%6,%7}, {%8,%9}, {%0,%1,%2,%3};"
        : "+f"(c[0]), "+f"(c[1]), "+f"(c[2]), "+f"(c[3])
        : "r"(a[0]), "r"(a[1]), "r"(a[2]), "r"(a[3]), "r"(b0), "r"(b1));
}

// ---------------- prep: split Q into bf16 hi/lo ------------------------------
__global__ __launch_bounds__(256) void qsplit_kernel(const float* __restrict__ Q) {
    size_t i = (size_t)blockIdx.x * 256 + threadIdx.x;   // handles 4 floats
    float4 v = ((const float4*)Q)[i];
    __nv_bfloat16 hx = __float2bfloat16(v.x), hy = __float2bfloat16(v.y);
    __nv_bfloat16 hz = __float2bfloat16(v.z), hw = __float2bfloat16(v.w);
    __nv_bfloat16 lx = __float2bfloat16(v.x - __bfloat162float(hx));
    __nv_bfloat16 ly = __float2bfloat16(v.y - __bfloat162float(hy));
    __nv_bfloat16 lz = __float2bfloat16(v.z - __bfloat162float(hz));
    __nv_bfloat16 lw = __float2bfloat16(v.w - __bfloat162float(hw));
    ((__nv_bfloat162*)g_qhi)[2 * i]     = __halves2bfloat162(hx, hy);
    ((__nv_bfloat162*)g_qhi)[2 * i + 1] = __halves2bfloat162(hz, hw);
    ((__nv_bfloat162*)g_qlo)[2 * i]     = __halves2bfloat162(lx, ly);
    ((__nv_bfloat162*)g_qlo)[2 * i + 1] = __halves2bfloat162(lz, lw);
}

// ---------------- prep: W^T + split ------------------------------------------
__global__ void wsplit_kernel(const float* __restrict__ W) {
    __shared__ float t[32][33];
    int bx = blockIdx.x * 32;   // d
    int by = blockIdx.y * 32;   // j
    int tx = threadIdx.x, ty0 = threadIdx.y;
#pragma unroll
    for (int i = 0; i < 4; i++) {
        int ty = ty0 + i * 8;
        t[ty][tx] = W[(size_t)(by + ty) * DIM + bx + tx];
    }
    __syncthreads();
#pragma unroll
    for (int i = 0; i < 4; i++) {
        int ty = ty0 + i * 8;
        float v = t[tx][ty];                     // = W[by+tx][bx+ty]
        __nv_bfloat16 h = __float2bfloat16(v);
        __nv_bfloat16 l = __float2bfloat16(v - __bfloat162float(h));
        size_t o = (size_t)(bx + ty) * DIM + by + tx;   // [d][j]
        g_wthi[o] = h;
        g_wtlo[o] = l;
    }
}

// ---------------- mma.sync GEMM: QT[16384,1024] = Q @ W ----------------------
// CTA 128(m) x 128(n). 8 warps = 2(m) x 4(n); warp tile 64x32.
// K chunked by 32, cp.async double-buffered. 3 term-pairs per chunk:
//   hi*hi, hi*lo, lo*hi  (all accumulate into the same fp32 C).
#define KC    32
#define KCP   40           // padded row stride in bf16 (80 B) -> conflict-free ldmatrix
#define TILEB (128 * KCP * 2)   // bytes per tile (10240)
#define STAGEB (4 * TILEB)      // Ah, Al, Bh, Bl     (40960)
#define SMEM_G (2 * STAGEB)     // double buffer      (81920)
#define NCH   (DIM / KC)        // 32

__device__ __forceinline__ void load_stage(uint32_t sst,
                                           const __nv_bfloat16* ah, const __nv_bfloat16* al,
                                           const __nv_bfloat16* bh, const __nv_bfloat16* bl,
                                           int kc0, int tid) {
    const __nv_bfloat16* srcs[4] = {ah, al, bh, bl};
#pragma unroll
    for (int t = 0; t < 4; t++) {
        const __nv_bfloat16* s = srcs[t] + kc0;
#pragma unroll
        for (int i = 0; i < 2; i++) {
            int flat = tid + i * 256;        // 0..511
            int r = flat >> 2, seg = flat & 3;
            CP_ASYNC16(sst + t * TILEB + r * 80 + seg * 16,
                       s + (size_t)r * DIM + seg * 8);
        }
    }
}

__global__ __launch_bounds__(256, 2) void qt_gemm_kernel() {
    extern __shared__ __align__(128) char smem[];
    const int tid  = threadIdx.x;
    const int wid  = tid >> 5, lane = tid & 31;
    const int bn   = blockIdx.x * 128;   // d tile
    const int bm   = blockIdx.y * 128;   // q tile
    const int wm   = (wid >> 2) * 64;
    const int wn   = (wid & 3) * 32;
    const uint32_t sb = smem_u32(smem);

    const __nv_bfloat16* qh = g_qhi  + (size_t)bm * DIM;
    const __nv_bfloat16* ql = g_qlo  + (size_t)bm * DIM;
    const __nv_bfloat16* wh = g_wthi + (size_t)bn * DIM;
    const __nv_bfloat16* wl = g_wtlo + (size_t)bn * DIM;

    float acc[4][4][4];
#pragma unroll
    for (int i = 0; i < 4; i++)
#pragma unroll
        for (int j = 0; j < 4; j++)
#pragma unroll
            for (int k = 0; k < 4; k++) acc[i][j][k] = 0.f;

    // per-lane ldmatrix offset: row = lane&15, k-halve = lane>>4
    const uint32_t lmo = (uint32_t)((lane & 15) * 80 + (lane >> 4) * 16);

    load_stage(sb, qh, ql, wh, wl, 0, tid);
    CP_COMMIT();

    for (int c = 0; c < NCH; c++) {
        const uint32_t sst = sb + (c & 1) * STAGEB;
        if (c + 1 < NCH) {
            load_stage(sb + ((c + 1) & 1) * STAGEB, qh, ql, wh, wl, (c + 1) * KC, tid);
            CP_COMMIT();
            CP_WAIT1();
        } else {
            CP_WAIT0();
        }
        __syncthreads();

        const uint32_t aH = sst + 0 * TILEB + wm * 80 + lmo;
        const uint32_t aL = sst + 1 * TILEB + wm * 80 + lmo;
        const uint32_t bH = sst + 2 * TILEB + wn * 80 + lmo;
        const uint32_t bL = sst + 3 * TILEB + wn * 80 + lmo;

#pragma unroll
        for (int kk = 0; kk < 2; kk++) {
            const uint32_t ko = kk * 32;   // 16 bf16 = 32 bytes
            uint32_t ah[4][4], bh2[2][4];
#pragma unroll
            for (int mi = 0; mi < 4; mi++)
                ldsm_x4(aH + mi * (16 * 80) + ko, ah[mi][0], ah[mi][1], ah[mi][2], ah[mi][3]);
#pragma unroll
            for (int ni = 0; ni < 2; ni++)
                ldsm_x4(bH + ni * (16 * 80) + ko, bh2[ni][0], bh2[ni][1], bh2[ni][2], bh2[ni][3]);
            // term 1: Ah * Bh
#pragma unroll
            for (int mi = 0; mi < 4; mi++)
#pragma unroll
                for (int g = 0; g < 4; g++) {
                    int ni = g >> 1, p = g & 1;
                    mma16816(acc[mi][g], ah[mi], bh2[ni][p], bh2[ni][2 + p]);
                }
            // term 2: Ah * Bl
            {
                uint32_t bl2[2][4];
#pragma unroll
                for (int ni = 0; ni < 2; ni++)
                    ldsm_x4(bL + ni * (16 * 80) + ko, bl2[ni][0], bl2[ni][1], bl2[ni][2], bl2[ni][3]);
#pragma unroll
                for (int mi = 0; mi < 4; mi++)
#pragma unroll
                    for (int g = 0; g < 4; g++) {
                        int ni = g >> 1, p = g & 1;
                        mma16816(acc[mi][g], ah[mi], bl2[ni][p], bl2[ni][2 + p]);
                    }
            }
            // term 3: Al * Bh
            {
                uint32_t al2[4][4];
#pragma unroll
                for (int mi = 0; mi < 4; mi++)
                    ldsm_x4(aL + mi * (16 * 80) + ko, al2[mi][0], al2[mi][1], al2[mi][2], al2[mi][3]);
#pragma unroll
                for (int mi = 0; mi < 4; mi++)
#pragma unroll
                    for (int g = 0; g < 4; g++) {
                        int ni = g >> 1, p = g & 1;
                        mma16816(acc[mi][g], al2[mi], bh2[ni][p], bh2[ni][2 + p]);
                    }
            }
        }
        __syncthreads();
    }

    // epilogue: acc -> g_qt
    const int qr = lane >> 2, qc = (lane & 3) * 2;
#pragma unroll
    for (int mi = 0; mi < 4; mi++) {
        const int row = bm + wm + mi * 16 + qr;
#pragma unroll
        for (int g = 0; g < 4; g++) {
            const int col = bn + wn + g * 8 + qc;
            *(float2*)(g_qt + (size_t)row * DIM + col) =
                make_float2(acc[mi][g][0], acc[mi][g][1]);
            *(float2*)(g_qt + (size_t)(row + 8) * DIM + col) =
                make_float2(acc[mi][g][2], acc[mi][g][3]);
        }
    }
}

// ---------------- banded attention (unchanged, validated R1) -----------------
#define QB   32
#define RT   72
#define RTA  80
#define DC   64
#define KSTR 68

__global__ __launch_bounds__(256) void band_attn_kernel(const float* __restrict__ keys,
                                                        float* __restrict__ out) {
    __shared__ float qts[QB][DC];
    __shared__ float ks[RTA][KSTR];
    __shared__ float sc[QB][48];

    const int tid = threadIdx.x;
    const int b   = blockIdx.y;
    const int q0  = blockIdx.x * QB;
    const size_t base = (size_t)b * SLEN * DIM;

    const int iq = tid >> 3;
    const int j0 = (tid & 7) * 6;

    float acc[6] = {0.f, 0.f, 0.f, 0.f, 0.f, 0.f};

    for (int dc = 0; dc < DIM; dc += DC) {
        __syncthreads();
        for (int f = tid; f < QB * DC / 4; f += 256) {
            int r = f >> 4, c = (f & 15) << 2;
            *(float4*)&qts[r][c] =
                *(const float4*)(g_qt + base + (size_t)(q0 + r) * DIM + dc + c);
        }
        for (int f = tid; f < RT * DC / 4; f += 256) {
            int r = f >> 4, c = (f & 15) << 2;
            int gr = q0 - WIN + r;
            float4 v = make_float4(0.f, 0.f, 0.f, 0.f);
            if (gr >= 0 && gr < SLEN)
                v = *(const float4*)(keys + base + (size_t)gr * DIM + dc + c);
            *(float4*)&ks[r][c] = v;
        }
        __syncthreads();
        for (int d = 0; d < DC; d += 4) {
            float4 qa = *(float4*)&qts[iq][d];
#pragma unroll
            for (int u = 0; u < 6; u++) {
                int r = iq + j0 + u;
                float4 kb = *(float4*)&ks[r][d];
                acc[u] = fmaf(qa.x, kb.x, acc[u]);
                acc[u] = fmaf(qa.y, kb.y, acc[u]);
                acc[u] = fmaf(qa.z, kb.z, acc[u]);
                acc[u] = fmaf(qa.w, kb.w, acc[u]);
            }
        }
    }
#pragma unroll
    for (int u = 0; u < 6; u++) {
        int j = j0 + u;
        if (j < NK) sc[iq][j] = acc[u];
    }
    __syncthreads();

    if (tid < QB) {
        int q = q0 + tid;
        float mx = -3.4e38f;
        for (int j = 0; j < NK; j++) {
            int k = q - WIN + j;
            if (k >= 0 && k < SLEN) mx = fmaxf(mx, sc[tid][j]);
        }
        float sum = 0.f;
        for (int j = 0; j < NK; j++) {
            int k = q - WIN + j;
            float e = 0.f;
            if (k >= 0 && k < SLEN) e = __expf(sc[tid][j] - mx);
            sc[tid][j] = e;
            sum += e;
        }
        float inv = 1.f / sum;
        for (int j = 0; j < NK; j++) sc[tid][j] *= inv;
    }

    const int ip = tid >> 3;
    const int g  = tid & 7;
    for (int dc = 0; dc < DIM; dc += DC) {
        __syncthreads();
        for (int f = tid; f < RT * DC / 4; f += 256) {
            int r = f >> 4, c = (f & 15) << 2;
            int gr = q0 - WIN + r;
            float4 v = make_float4(0.f, 0.f, 0.f, 0.f);
            if (gr >= 0 && gr < SLEN)
                v = *(const float4*)(keys + base + (size_t)gr * DIM + dc + c);
            *(float4*)&ks[r][c] = v;
        }
        __syncthreads();
        for (int dd = g * 4; dd < DC; dd += 32) {
            float4 o = make_float4(0.f, 0.f, 0.f, 0.f);
#pragma unroll
            for (int j = 0; j < NK; j++) {
                float w = sc[ip][j];
                float4 kv = *(float4*)&ks[ip + j][dd];
                o.x = fmaf(w, kv.x, o.x);
                o.y = fmaf(w, kv.y, o.y);
                o.z = fmaf(w, kv.z, o.z);
                o.w = fmaf(w, kv.w, o.w);
            }
            *(float4*)(out + base + (size_t)(q0 + ip) * DIM + dc + dd) = o;
        }
    }
}

extern "C" void kernel_launch(void* const* d_in, const int* in_sizes, int n_in,
                              void* d_out, int out_size) {
    const float* queries = (const float*)d_in[0];
    const float* keys    = (const float*)d_in[1];
    const float* W       = (const float*)d_in[2];
    // d_in[3] = b_reduce: per-(b,q) constant added to all logits -> softmax-invariant, unused.
    float* out = (float*)d_out;

    cudaFuncSetAttribute(qt_gemm_kernel, cudaFuncAttributeMaxDynamicSharedMemorySize, SMEM_G);

    qsplit_kernel<<<(MTOT * DIM) / 4 / 256, 256>>>(queries);
    wsplit_kernel<<<dim3(DIM / 32, DIM / 32), dim3(32, 8)>>>(W);

    dim3 gg(DIM / 128, MTOT / 128);
    qt_gemm_kernel<<<gg, 256, SMEM_G>>>();

    dim3 g2(SLEN / QB, BATCH);
    band_attn_kernel<<<g2, 256>>>(keys, out);
}

// round 4
// speedup vs baseline: 2.4231x; 1.6043x over previous
#include <cuda_runtime.h>
#include <cuda_bf16.h>
#include <cstdint>

#define BATCH 8
#define SLEN  2048
#define DIM   1024
#define WIN   20
#define MTOT  (BATCH * SLEN)   // 16384

// ---------------- static device scratch -------------------------------------
__device__ __nv_bfloat16 g_qhi [(size_t)MTOT * DIM];
__device__ __nv_bfloat16 g_qlo [(size_t)MTOT * DIM];
__device__ __nv_bfloat16 g_wthi[(size_t)DIM * DIM];   // W^T split: [d][j]
__device__ __nv_bfloat16 g_wtlo[(size_t)DIM * DIM];
__device__ __nv_bfloat16 g_qthi[(size_t)MTOT * DIM];  // QT = Q@W, bf16 split
__device__ __nv_bfloat16 g_qtlo[(size_t)MTOT * DIM];
__device__ __nv_bfloat16 g_khi [(size_t)MTOT * DIM];  // keys split
__device__ __nv_bfloat16 g_klo [(size_t)MTOT * DIM];

// ---------------- helpers ----------------------------------------------------
__device__ __forceinline__ uint32_t smem_u32(const void* p) {
    uint32_t a;
    asm("{ .reg .u64 t; cvta.to.shared.u64 t, %1; cvt.u32.u64 %0, t; }" : "=r"(a) : "l"(p));
    return a;
}
#define CP_ASYNC16(sd, gp) \
    asm volatile("cp.async.cg.shared.global [%0], [%1], 16;" :: "r"(sd), "l"(gp) : "memory")
#define CP_COMMIT()   asm volatile("cp.async.commit_group;" ::: "memory")
#define CP_WAIT0()    asm volatile("cp.async.wait_group 0;" ::: "memory")
#define CP_WAIT1()    asm volatile("cp.async.wait_group 1;" ::: "memory")
#define ST_SHARED_ZERO16(a) \
    asm volatile("st.shared.v4.b32 [%0], {%1,%1,%1,%1};" :: "r"(a), "r"(0) : "memory")

__device__ __forceinline__ void ldsm_x4(uint32_t a, uint32_t& r0, uint32_t& r1,
                                        uint32_t& r2, uint32_t& r3) {
    asm volatile("ldmatrix.sync.aligned.m8n8.x4.shared.b16 {%0,%1,%2,%3}, [%4];"
                 : "=r"(r0), "=r"(r1), "=r"(r2), "=r"(r3) : "r"(a));
}
__device__ __forceinline__ void ldsm_x4_t(uint32_t a, uint32_t& r0, uint32_t& r1,
                                          uint32_t& r2, uint32_t& r3) {
    asm volatile("ldmatrix.sync.aligned.m8n8.x4.trans.shared.b16 {%0,%1,%2,%3}, [%4];"
                 : "=r"(r0), "=r"(r1), "=r"(r2), "=r"(r3) : "r"(a));
}
__device__ __forceinline__ void mma16816(float* c, const uint32_t* a,
                                         uint32_t b0, uint32_t b1) {
    asm volatile(
        "mma.sync.aligned.m16n8k16.row.col.f32.bf16.bf16.f32 "
        "{%0,%1,%2,%3}, {%4,%5,%6,%7}, {%8,%9}, {%0,%1,%2,%3};"
        : "+f"(c[0]), "+f"(c[1]), "+f"(c[2]), "+f"(c[3])
        : "r"(a[0]), "r"(a[1]), "r"(a[2]), "r"(a[3]), "r"(b0), "r"(b1));
}

// ---------------- prep: fp32 -> bf16 hi/lo split ------------------------------
__global__ __launch_bounds__(256) void split_kernel(const float* __restrict__ src,
                                                    __nv_bfloat16* __restrict__ hi,
                                                    __nv_bfloat16* __restrict__ lo) {
    size_t i = (size_t)blockIdx.x * 256 + threadIdx.x;   // handles 4 floats
    float4 v = ((const float4*)src)[i];
    __nv_bfloat16 hx = __float2bfloat16(v.x), hy = __float2bfloat16(v.y);
    __nv_bfloat16 hz = __float2bfloat16(v.z), hw = __float2bfloat16(v.w);
    __nv_bfloat16 lx = __float2bfloat16(v.x - __bfloat162float(hx));
    __nv_bfloat16 ly = __float2bfloat16(v.y - __bfloat162float(hy));
    __nv_bfloat16 lz = __float2bfloat16(v.z - __bfloat162float(hz));
    __nv_bfloat16 lw = __float2bfloat16(v.w - __bfloat162float(hw));
    ((__nv_bfloat162*)hi)[2 * i]     = __halves2bfloat162(hx, hy);
    ((__nv_bfloat162*)hi)[2 * i + 1] = __halves2bfloat162(hz, hw);
    ((__nv_bfloat162*)lo)[2 * i]     = __halves2bfloat162(lx, ly);
    ((__nv_bfloat162*)lo)[2 * i + 1] = __halves2bfloat162(lz, lw);
}

// ---------------- prep: W^T + split ------------------------------------------
__global__ void wsplit_kernel(const float* __restrict__ W) {
    __shared__ float t[32][33];
    int bx = blockIdx.x * 32;   // d
    int by = blockIdx.y * 32;   // j
    int tx = threadIdx.x, ty0 = threadIdx.y;
#pragma unroll
    for (int i = 0; i < 4; i++) {
        int ty = ty0 + i * 8;
        t[ty][tx] = W[(size_t)(by + ty) * DIM + bx + tx];
    }
    __syncthreads();
#pragma unroll
    for (int i = 0; i < 4; i++) {
        int ty = ty0 + i * 8;
        float v = t[tx][ty];                     // = W[by+tx][bx+ty]
        __nv_bfloat16 h = __float2bfloat16(v);
        __nv_bfloat16 l = __float2bfloat16(v - __bfloat162float(h));
        size_t o = (size_t)(bx + ty) * DIM + by + tx;   // [d][j]
        g_wthi[o] = h;
        g_wtlo[o] = l;
    }
}

// ---------------- mma.sync GEMM: QT = Q @ W  (epilogue -> bf16 split) ---------
#define KC    32
#define TILEB (128 * 40 * 2)     // 10240 (stride 80B/row)
#define STAGEB (4 * TILEB)
#define SMEM_G (2 * STAGEB)
#define NCH   (DIM / KC)

__device__ __forceinline__ void load_stage(uint32_t sst,
                                           const __nv_bfloat16* ah, const __nv_bfloat16* al,
                                           const __nv_bfloat16* bh, const __nv_bfloat16* bl,
                                           int kc0, int tid) {
    const __nv_bfloat16* srcs[4] = {ah, al, bh, bl};
#pragma unroll
    for (int t = 0; t < 4; t++) {
        const __nv_bfloat16* s = srcs[t] + kc0;
#pragma unroll
        for (int i = 0; i < 2; i++) {
            int flat = tid + i * 256;
            int r = flat >> 2, seg = flat & 3;
            CP_ASYNC16(sst + t * TILEB + r * 80 + seg * 16,
                       s + (size_t)r * DIM + seg * 8);
        }
    }
}

__global__ __launch_bounds__(256, 2) void qt_gemm_kernel() {
    extern __shared__ __align__(128) char smem[];
    const int tid  = threadIdx.x;
    const int wid  = tid >> 5, lane = tid & 31;
    const int bn   = blockIdx.x * 128;
    const int bm   = blockIdx.y * 128;
    const int wm   = (wid >> 2) * 64;
    const int wn   = (wid & 3) * 32;
    const uint32_t sb = smem_u32(smem);

    const __nv_bfloat16* qh = g_qhi  + (size_t)bm * DIM;
    const __nv_bfloat16* ql = g_qlo  + (size_t)bm * DIM;
    const __nv_bfloat16* wh = g_wthi + (size_t)bn * DIM;
    const __nv_bfloat16* wl = g_wtlo + (size_t)bn * DIM;

    float acc[4][4][4];
#pragma unroll
    for (int i = 0; i < 4; i++)
#pragma unroll
        for (int j = 0; j < 4; j++)
#pragma unroll
            for (int k = 0; k < 4; k++) acc[i][j][k] = 0.f;

    const uint32_t lmo = (uint32_t)((lane & 15) * 80 + (lane >> 4) * 16);

    load_stage(sb, qh, ql, wh, wl, 0, tid);
    CP_COMMIT();

    for (int c = 0; c < NCH; c++) {
        const uint32_t sst = sb + (c & 1) * STAGEB;
        if (c + 1 < NCH) {
            load_stage(sb + ((c + 1) & 1) * STAGEB, qh, ql, wh, wl, (c + 1) * KC, tid);
            CP_COMMIT();
            CP_WAIT1();
        } else {
            CP_WAIT0();
        }
        __syncthreads();

        const uint32_t aH = sst + 0 * TILEB + wm * 80 + lmo;
        const uint32_t aL = sst + 1 * TILEB + wm * 80 + lmo;
        const uint32_t bH = sst + 2 * TILEB + wn * 80 + lmo;
        const uint32_t bL = sst + 3 * TILEB + wn * 80 + lmo;

#pragma unroll
        for (int kk = 0; kk < 2; kk++) {
            const uint32_t ko = kk * 32;
            uint32_t ah[4][4], bh2[2][4];
#pragma unroll
            for (int mi = 0; mi < 4; mi++)
                ldsm_x4(aH + mi * (16 * 80) + ko, ah[mi][0], ah[mi][1], ah[mi][2], ah[mi][3]);
#pragma unroll
            for (int ni = 0; ni < 2; ni++)
                ldsm_x4(bH + ni * (16 * 80) + ko, bh2[ni][0], bh2[ni][1], bh2[ni][2], bh2[ni][3]);
#pragma unroll
            for (int mi = 0; mi < 4; mi++)
#pragma unroll
                for (int g = 0; g < 4; g++) {
                    int ni = g >> 1, p = g & 1;
                    mma16816(acc[mi][g], ah[mi], bh2[ni][p], bh2[ni][2 + p]);
                }
            {
                uint32_t bl2[2][4];
#pragma unroll
                for (int ni = 0; ni < 2; ni++)
                    ldsm_x4(bL + ni * (16 * 80) + ko, bl2[ni][0], bl2[ni][1], bl2[ni][2], bl2[ni][3]);
#pragma unroll
                for (int mi = 0; mi < 4; mi++)
#pragma unroll
                    for (int g = 0; g < 4; g++) {
                        int ni = g >> 1, p = g & 1;
                        mma16816(acc[mi][g], ah[mi], bl2[ni][p], bl2[ni][2 + p]);
                    }
            }
            {
                uint32_t al2[4][4];
#pragma unroll
                for (int mi = 0; mi < 4; mi++)
                    ldsm_x4(aL + mi * (16 * 80) + ko, al2[mi][0], al2[mi][1], al2[mi][2], al2[mi][3]);
#pragma unroll
                for (int mi = 0; mi < 4; mi++)
#pragma unroll
                    for (int g = 0; g < 4; g++) {
                        int ni = g >> 1, p = g & 1;
                        mma16816(acc[mi][g], al2[mi], bh2[ni][p], bh2[ni][2 + p]);
                    }
            }
        }
        __syncthreads();
    }

    // epilogue: acc -> bf16 hi/lo split
    const int qr = lane >> 2, qc = (lane & 3) * 2;
#pragma unroll
    for (int mi = 0; mi < 4; mi++) {
        const int row = bm + wm + mi * 16 + qr;
#pragma unroll
        for (int g = 0; g < 4; g++) {
            const int col = bn + wn + g * 8 + qc;
#pragma unroll
            for (int half = 0; half < 2; half++) {
                float c0 = acc[mi][g][half * 2], c1 = acc[mi][g][half * 2 + 1];
                __nv_bfloat16 h0 = __float2bfloat16(c0);
                __nv_bfloat16 h1 = __float2bfloat16(c1);
                __nv_bfloat16 l0 = __float2bfloat16(c0 - __bfloat162float(h0));
                __nv_bfloat16 l1 = __float2bfloat16(c1 - __bfloat162float(h1));
                size_t o = ((size_t)(row + half * 8) * DIM + col) / 2;
                ((__nv_bfloat162*)g_qthi)[o] = __halves2bfloat162(h0, h1);
                ((__nv_bfloat162*)g_qtlo)[o] = __halves2bfloat162(l0, l1);
            }
        }
    }
}

// ---------------- banded attention via mma.sync -------------------------------
// Per CTA: 64 queries (one batch) x 128-key dense tile (band masked at softmax).
#define QB2    64
#define KRN    128           // key rows in tile (n of score mma)
#define KSTRB  144           // K/QT tile row stride bytes (64 bf16 + 16B pad)
#define PSTRB  240           // P tile row stride bytes (120 bf16)
#define SSTR   132           // S row stride in floats

#define OFF_KH 0u
#define OFF_KL 18432u        // 128*144
#define OFF_QH 36864u
#define OFF_QL 46080u        // +64*144
#define OFF_S  0u            // overlays K/QT region (dead between phases)
#define OFF_PH 55296u
#define OFF_PL 70656u        // +64*240
#define SMEM_B 86016u

__device__ __forceinline__ void load_ktile(uint32_t sb, int q0, size_t kbase,
                                           int dc, int tid) {
#pragma unroll
    for (int i = 0; i < 4; i++) {
        int flat = tid + i * 256;           // 0..1023
        int r = flat >> 3, seg = flat & 7;
        int kr = q0 - WIN + r;
        uint32_t sh = sb + OFF_KH + (uint32_t)(r * KSTRB + seg * 16);
        uint32_t sl = sb + OFF_KL + (uint32_t)(r * KSTRB + seg * 16);
        if ((unsigned)kr < SLEN) {
            size_t go = kbase + (size_t)kr * DIM + dc + seg * 8;
            CP_ASYNC16(sh, g_khi + go);
            CP_ASYNC16(sl, g_klo + go);
        } else {
            ST_SHARED_ZERO16(sh);
            ST_SHARED_ZERO16(sl);
        }
    }
}

__global__ __launch_bounds__(256, 2) void band_attn_kernel(float* __restrict__ out) {
    extern __shared__ __align__(128) char smem[];
    const uint32_t sb = smem_u32(smem);
    const int tid = threadIdx.x, wid = tid >> 5, lane = tid & 31;
    const int b = blockIdx.y, q0 = blockIdx.x * QB2;
    const size_t kbase  = (size_t)b * SLEN * DIM;
    const size_t qtbase = ((size_t)b * SLEN + q0) * DIM;

    const int wm  = (wid >> 1) * 16;     // 4 m-warps: 16 query rows each
    const int wn  = (wid & 1) * 64;      // 2 n-warps: 64 key cols each (phase 1)
    const int wn3 = (wid & 1) * 32;      // 2 n-warps: 32 d cols each (phase 3)

    // ---------------- phase 1: S = QT . K^T (3-term bf16 split) ------------
    float acc[8][4];
#pragma unroll
    for (int i = 0; i < 8; i++)
#pragma unroll
        for (int j = 0; j < 4; j++) acc[i][j] = 0.f;

    const uint32_t lmoA = (uint32_t)((wm + (lane & 15)) * KSTRB + (lane >> 4) * 16);
    const uint32_t lmoB = (uint32_t)((lane & 15) * KSTRB + (lane >> 4) * 16);

    for (int ch = 0; ch < 16; ch++) {
        const int dc = ch * 64;
#pragma unroll
        for (int i = 0; i < 2; i++) {                 // QT tiles (64 rows)
            int flat = tid + i * 256;
            int r = flat >> 3, seg = flat & 7;
            size_t go = qtbase + (size_t)r * DIM + dc + seg * 8;
            uint32_t so = (uint32_t)(r * KSTRB + seg * 16);
            CP_ASYNC16(sb + OFF_QH + so, g_qthi + go);
            CP_ASYNC16(sb + OFF_QL + so, g_qtlo + go);
        }
        load_ktile(sb, q0, kbase, dc, tid);
        CP_COMMIT();
        CP_WAIT0();
        __syncthreads();

#pragma unroll
        for (int ks = 0; ks < 4; ks++) {
            const uint32_t ko = ks * 32;
            uint32_t ah[4], al[4], bh[4][4], bl[4][4];
            ldsm_x4(sb + OFF_QH + lmoA + ko, ah[0], ah[1], ah[2], ah[3]);
            ldsm_x4(sb + OFF_QL + lmoA + ko, al[0], al[1], al[2], al[3]);
#pragma unroll
            for (int g = 0; g < 4; g++) {
                uint32_t ba = (uint32_t)((wn + g * 16) * KSTRB) + lmoB + ko;
                ldsm_x4(sb + OFF_KH + ba, bh[g][0], bh[g][1], bh[g][2], bh[g][3]);
                ldsm_x4(sb + OFF_KL + ba, bl[g][0], bl[g][1], bl[g][2], bl[g][3]);
            }
#pragma unroll
            for (int nf = 0; nf < 8; nf++) {
                int g = nf >> 1, p = nf & 1;
                mma16816(acc[nf], ah, bh[g][p], bh[g][2 + p]);
            }
#pragma unroll
            for (int nf = 0; nf < 8; nf++) {
                int g = nf >> 1, p = nf & 1;
                mma16816(acc[nf], ah, bl[g][p], bl[g][2 + p]);
            }
#pragma unroll
            for (int nf = 0; nf < 8; nf++) {
                int g = nf >> 1, p = nf & 1;
                mma16816(acc[nf], al, bh[g][p], bh[g][2 + p]);
            }
        }
        __syncthreads();
    }

    // ---------------- S frags -> smem ---------------------------------------
    {
        float* S = (float*)(smem + OFF_S);
        int r0 = wm + (lane >> 2);
        int c0 = wn + (lane & 3) * 2;
#pragma unroll
        for (int nf = 0; nf < 8; nf++) {
            int c = c0 + nf * 8;
            *(float2*)&S[r0 * SSTR + c]       = make_float2(acc[nf][0], acc[nf][1]);
            *(float2*)&S[(r0 + 8) * SSTR + c] = make_float2(acc[nf][2], acc[nf][3]);
        }
    }
    __syncthreads();

    // ---------------- softmax (band + boundary mask) ------------------------
    {
        float* S = (float*)(smem + OFF_S);
        __nv_bfloat16* PH = (__nv_bfloat16*)(smem + OFF_PH);
        __nv_bfloat16* PL = (__nv_bfloat16*)(smem + OFF_PL);
        const int row = tid >> 2, part = tid & 3;
        int rmin = row;
        int t = WIN - q0;               // kr >= 0
        if (t > rmin) rmin = t;
        int rmax = row + 2 * WIN;
        t = (SLEN - 1) + WIN - q0;      // kr <= SLEN-1
        if (t < rmax) rmax = t;
        const int cbeg = part * 32, cend = cbeg + 32;

        float mx = -3.4e38f;
        for (int c = cbeg; c < cend; c++)
            if (c >= rmin && c <= rmax) mx = fmaxf(mx, S[row * SSTR + c]);
        mx = fmaxf(mx, __shfl_xor_sync(0xFFFFFFFFu, mx, 1));
        mx = fmaxf(mx, __shfl_xor_sync(0xFFFFFFFFu, mx, 2));

        float sum = 0.f;
        for (int c = cbeg; c < cend; c++) {
            float e = (c >= rmin && c <= rmax) ? __expf(S[row * SSTR + c] - mx) : 0.f;
            S[row * SSTR + c] = e;
            sum += e;
        }
        sum += __shfl_xor_sync(0xFFFFFFFFu, sum, 1);
        sum += __shfl_xor_sync(0xFFFFFFFFu, sum, 2);
        const float inv = 1.f / sum;

        for (int c = cbeg; c < cend && c < 112; c++) {
            float p = S[row * SSTR + c] * inv;
            __nv_bfloat16 h = __float2bfloat16(p);
            __nv_bfloat16 l = __float2bfloat16(p - __bfloat162float(h));
            PH[row * 120 + c] = h;
            PL[row * 120 + c] = l;
        }
    }
    __syncthreads();

    // ---------------- phase 3: O = P . K  (3-term split, trans B) -----------
    const uint32_t lmoP = (uint32_t)((wm + (lane & 15)) * PSTRB + (lane >> 4) * 16);
    for (int ch = 0; ch < 16; ch++) {
        const int dc = ch * 64;
        load_ktile(sb, q0, kbase, dc, tid);
        CP_COMMIT();
        CP_WAIT0();
        __syncthreads();

        float oacc[4][4];
#pragma unroll
        for (int i = 0; i < 4; i++)
#pragma unroll
            for (int j = 0; j < 4; j++) oacc[i][j] = 0.f;

#pragma unroll
        for (int ks = 0; ks < 7; ks++) {
            uint32_t ah[4], al[4], bh[2][4], bl[2][4];
            ldsm_x4(sb + OFF_PH + lmoP + ks * 32, ah[0], ah[1], ah[2], ah[3]);
            ldsm_x4(sb + OFF_PL + lmoP + ks * 32, al[0], al[1], al[2], al[3]);
#pragma unroll
            for (int g = 0; g < 2; g++) {
                uint32_t ba = (uint32_t)((ks * 16 + (lane & 15)) * KSTRB +
                                         wn3 * 2 + g * 32 + (lane >> 4) * 16);
                ldsm_x4_t(sb + OFF_KH + ba, bh[g][0], bh[g][1], bh[g][2], bh[g][3]);
                ldsm_x4_t(sb + OFF_KL + ba, bl[g][0], bl[g][1], bl[g][2], bl[g][3]);
            }
#pragma unroll
            for (int nf = 0; nf < 4; nf++) {
                int g = nf >> 1, p = nf & 1;
                mma16816(oacc[nf], ah, bh[g][2 * p], bh[g][2 * p + 1]);
            }
#pragma unroll
            for (int nf = 0; nf < 4; nf++) {
                int g = nf >> 1, p = nf & 1;
                mma16816(oacc[nf], ah, bl[g][2 * p], bl[g][2 * p + 1]);
            }
#pragma unroll
            for (int nf = 0; nf < 4; nf++) {
                int g = nf >> 1, p = nf & 1;
                mma16816(oacc[nf], al, bh[g][2 * p], bh[g][2 * p + 1]);
            }
        }

        const int r0 = q0 + wm + (lane >> 2);
        const int c0 = dc + wn3 + (lane & 3) * 2;
#pragma unroll
        for (int nf = 0; nf < 4; nf++) {
            int c = c0 + nf * 8;
            *(float2*)(out + kbase + (size_t)r0 * DIM + c) =
                make_float2(oacc[nf][0], oacc[nf][1]);
            *(float2*)(out + kbase + (size_t)(r0 + 8) * DIM + c) =
                make_float2(oacc[nf][2], oacc[nf][3]);
        }
        __syncthreads();
    }
}

extern "C" void kernel_launch(void* const* d_in, const int* in_sizes, int n_in,
                              void* d_out, int out_size) {
    const float* queries = (const float*)d_in[0];
    const float* keys    = (const float*)d_in[1];
    const float* W       = (const float*)d_in[2];
    // d_in[3] = b_reduce: per-(b,q) constant added to all logits -> softmax-invariant, unused.
    float* out = (float*)d_out;

    void *p_qhi, *p_qlo, *p_khi, *p_klo;
    cudaGetSymbolAddress(&p_qhi, g_qhi);
    cudaGetSymbolAddress(&p_qlo, g_qlo);
    cudaGetSymbolAddress(&p_khi, g_khi);
    cudaGetSymbolAddress(&p_klo, g_klo);

    cudaFuncSetAttribute(qt_gemm_kernel, cudaFuncAttributeMaxDynamicSharedMemorySize, SMEM_G);
    cudaFuncSetAttribute(band_attn_kernel, cudaFuncAttributeMaxDynamicSharedMemorySize, SMEM_B);

    const int splitGrid = (MTOT * DIM) / 4 / 256;
    split_kernel<<<splitGrid, 256>>>(queries, (__nv_bfloat16*)p_qhi, (__nv_bfloat16*)p_qlo);
    split_kernel<<<splitGrid, 256>>>(keys, (__nv_bfloat16*)p_khi, (__nv_bfloat16*)p_klo);
    wsplit_kernel<<<dim3(DIM / 32, DIM / 32), dim3(32, 8)>>>(W);

    dim3 gg(DIM / 128, MTOT / 128);
    qt_gemm_kernel<<<gg, 256, SMEM_G>>>();

    dim3 g2(SLEN / QB2, BATCH);
    band_attn_kernel<<<g2, 256, SMEM_B>>>(out);
}